// round 4
// baseline (speedup 1.0000x reference)
#include <cuda_runtime.h>
#include <math.h>

typedef unsigned long long u64;

// Problem constants
constexpr int D     = 768;
constexpr int SQ    = 2048;
constexpr int BATCH = 4;
constexpr int NH    = 12;
constexpr int HDIM  = 64;
constexpr int MTOT  = BATCH * SQ;   // 8192 rows

// Scratch (alloc-free rule: __device__ globals)
__device__ float g_Q[MTOT * D];
__device__ float g_K[MTOT * D];
__device__ float g_V[MTOT * D];
__device__ float g_ctx[MTOT * D];

// ---- packed f32x2 helpers ------------------------------------------------
__device__ __forceinline__ u64 splat2(float x) {
    u64 r; unsigned xi = __float_as_uint(x);
    asm("mov.b64 %0, {%1, %1};" : "=l"(r) : "r"(xi));
    return r;
}
__device__ __forceinline__ void ffma2(u64 &d, u64 a, u64 b) {
    asm("fma.rn.f32x2 %0, %1, %2, %0;" : "+l"(d) : "l"(a), "l"(b));
}
__device__ __forceinline__ u64 fmul2(u64 a, u64 b) {
    u64 r; asm("mul.rn.f32x2 %0, %1, %2;" : "=l"(r) : "l"(a), "l"(b));
    return r;
}
__device__ __forceinline__ float2 unpack2(u64 v) {
    float2 f;
    asm("mov.b64 {%0, %1}, %2;" : "=f"(f.x), "=f"(f.y) : "l"(v));
    return f;
}
__device__ __forceinline__ u64 dtou(double d) { return __double_as_longlong(d); }

// ---------------------------------------------------------------------------
// GEMM: C[m][n] = sum_k A[m][k] * W[n][k] + bias[n]
// M=8192, N=768, K=768. BM=BN=128, BK=16, 256 threads.
// Per thread: 8 rows (4 packed pairs) x 8 cols (tx*4 and 64+tx*4 halves).
// ---------------------------------------------------------------------------
constexpr int BM = 128, BN = 128, BK = 16, BMP = 132;

__device__ __forceinline__ void gemm_nt(const float* __restrict__ A,
                                        const float* __restrict__ W,
                                        const float* __restrict__ bias,
                                        float* __restrict__ C) {
    __shared__ __align__(16) float As[BK][BMP];   // [k][m]
    __shared__ __align__(16) float Bs[BK][BMP];   // [k][n]
    const int tid = threadIdx.x;
    const int tx = tid & 15, ty = tid >> 4;
    const int m0 = blockIdx.y * BM, n0 = blockIdx.x * BN;
    const int lm = tid >> 1;          // 0..127
    const int lk = (tid & 1) * 8;     // 0 or 8
    const float* Ap = A + (size_t)(m0 + lm) * D + lk;
    const float* Wp = W + (size_t)(n0 + lm) * D + lk;

    u64 acc[4][8];
#pragma unroll
    for (int i = 0; i < 4; i++)
#pragma unroll
        for (int j = 0; j < 8; j++) acc[i][j] = 0ull;

    float4 ra0 = *(const float4*)(Ap);
    float4 ra1 = *(const float4*)(Ap + 4);
    float4 rb0 = *(const float4*)(Wp);
    float4 rb1 = *(const float4*)(Wp + 4);

    for (int kt = 0; kt < D; kt += BK) {
        As[lk + 0][lm] = ra0.x; As[lk + 1][lm] = ra0.y;
        As[lk + 2][lm] = ra0.z; As[lk + 3][lm] = ra0.w;
        As[lk + 4][lm] = ra1.x; As[lk + 5][lm] = ra1.y;
        As[lk + 6][lm] = ra1.z; As[lk + 7][lm] = ra1.w;
        Bs[lk + 0][lm] = rb0.x; Bs[lk + 1][lm] = rb0.y;
        Bs[lk + 2][lm] = rb0.z; Bs[lk + 3][lm] = rb0.w;
        Bs[lk + 4][lm] = rb1.x; Bs[lk + 5][lm] = rb1.y;
        Bs[lk + 6][lm] = rb1.z; Bs[lk + 7][lm] = rb1.w;
        __syncthreads();
        if (kt + BK < D) {   // prefetch next tile
            ra0 = *(const float4*)(Ap + kt + BK);
            ra1 = *(const float4*)(Ap + kt + BK + 4);
            rb0 = *(const float4*)(Wp + kt + BK);
            rb1 = *(const float4*)(Wp + kt + BK + 4);
        }
#pragma unroll
        for (int kk = 0; kk < BK; kk++) {
            double2 A0 = *(const double2*)&As[kk][ty * 8];      // row pairs 0-1, 2-3
            double2 A1 = *(const double2*)&As[kk][ty * 8 + 4];  // row pairs 4-5, 6-7
            float4 B0 = *(const float4*)&Bs[kk][tx * 4];
            float4 B1 = *(const float4*)&Bs[kk][64 + tx * 4];
            u64 a[4] = {dtou(A0.x), dtou(A0.y), dtou(A1.x), dtou(A1.y)};
            u64 b[8] = {splat2(B0.x), splat2(B0.y), splat2(B0.z), splat2(B0.w),
                        splat2(B1.x), splat2(B1.y), splat2(B1.z), splat2(B1.w)};
#pragma unroll
            for (int i = 0; i < 4; i++)
#pragma unroll
                for (int j = 0; j < 8; j++)
                    ffma2(acc[i][j], a[i], b[j]);
        }
        __syncthreads();
    }

    float bb[8];
#pragma unroll
    for (int j = 0; j < 4; j++) bb[j] = bias[n0 + tx * 4 + j];
#pragma unroll
    for (int j = 0; j < 4; j++) bb[4 + j] = bias[n0 + 64 + tx * 4 + j];

#pragma unroll
    for (int i2 = 0; i2 < 4; i2++) {
        float lo[8], hi[8];
#pragma unroll
        for (int j = 0; j < 8; j++) {
            float2 v = unpack2(acc[i2][j]);
            lo[j] = v.x + bb[j];
            hi[j] = v.y + bb[j];
        }
        float* r0 = C + (size_t)(m0 + ty * 8 + 2 * i2) * D + n0;
        float* r1 = r0 + D;
        *(float4*)(r0 + tx * 4)      = make_float4(lo[0], lo[1], lo[2], lo[3]);
        *(float4*)(r0 + 64 + tx * 4) = make_float4(lo[4], lo[5], lo[6], lo[7]);
        *(float4*)(r1 + tx * 4)      = make_float4(hi[0], hi[1], hi[2], hi[3]);
        *(float4*)(r1 + 64 + tx * 4) = make_float4(hi[4], hi[5], hi[6], hi[7]);
    }
}

__global__ void __launch_bounds__(256, 2)
qkv_gemm(const float* __restrict__ x,
         const float* __restrict__ Wq, const float* __restrict__ bq,
         const float* __restrict__ Wk, const float* __restrict__ bk,
         const float* __restrict__ Wv, const float* __restrict__ bv) {
    const float* W; const float* bias; float* C;
    if (blockIdx.z == 0)      { W = Wq; bias = bq; C = g_Q; }
    else if (blockIdx.z == 1) { W = Wk; bias = bk; C = g_K; }
    else                      { W = Wv; bias = bv; C = g_V; }
    gemm_nt(x, W, bias, C);
}

__global__ void __launch_bounds__(256, 2)
out_gemm(const float* __restrict__ Wo, const float* __restrict__ bo,
         float* __restrict__ out) {
    gemm_nt(g_ctx, Wo, bo, out);
}

// ---------------------------------------------------------------------------
// Flash attention: grid (16 q-tiles, 48 bh), 256 threads.
// 128 q-rows per block, 64 kv per iteration, hd=64. Packed f32x2 math.
// Softmax writes P duplicated (p,p) so PV phase reads splats via LDS.64.
// ---------------------------------------------------------------------------
constexpr int QP  = 132;   // Qs row pad (d-major, 128 q rows)
constexpr int KP  = 68;    // Ks/Vs pad
constexpr int SP  = 68;    // Ss pad (raw scores)
constexpr int PDP = 132;   // Pd pad (duplicated P, 128 floats + 4)
constexpr int ATTN_SMEM_FLOATS =
    64 * QP + 64 * KP + 64 * KP + 128 * SP + 128 * PDP + 256;
constexpr int ATTN_SMEM_BYTES = ATTN_SMEM_FLOATS * 4;   // ~172 KB

__global__ void __launch_bounds__(256)
attn_kernel() {
    extern __shared__ __align__(16) float sm[];
    float* Qs = sm;                                // [d][r] d-major
    float* Ks = Qs + 64 * QP;                      // [d][c] d-major
    float* Vs = Ks + 64 * KP;                      // [j][d] row-major
    float* Ss = Vs + 64 * KP;                      // [r][c] raw scores
    float* Pd = Ss + 128 * SP;                     // [r][2c] duplicated probs
    float* alpha_s = Pd + 128 * PDP;               // [128]
    float* l_s     = alpha_s + 128;                // [128]

    const int tid = threadIdx.x;
    const int tx = tid & 15, ty = tid >> 4;
    const int bh = blockIdx.y;
    const int b = bh / NH, h = bh % NH;
    const int q0 = blockIdx.x * 128;

    const float* Qb = g_Q + (size_t)(b * SQ) * D + h * HDIM;
    const float* Kb = g_K + (size_t)(b * SQ) * D + h * HDIM;
    const float* Vb = g_V + (size_t)(b * SQ) * D + h * HDIM;

    // Load Q tile (128 x 64) transposed to d-major, scale folded in
    {
        const int lr = tid >> 1;
        const int ld0 = (tid & 1) * 32;
        const float* qrow = Qb + (size_t)(q0 + lr) * D + ld0;
#pragma unroll
        for (int i4 = 0; i4 < 8; i4++) {
            float4 v = *(const float4*)(qrow + i4 * 4);
            int d = ld0 + i4 * 4;
            Qs[(d + 0) * QP + lr] = v.x * 0.125f;
            Qs[(d + 1) * QP + lr] = v.y * 0.125f;
            Qs[(d + 2) * QP + lr] = v.z * 0.125f;
            Qs[(d + 3) * QP + lr] = v.w * 0.125f;
        }
    }

    float m_team = -INFINITY, l_team = 0.0f;      // per-row state (row = tid>>1)
    u64 acc[8][2];                                 // 8 rows x 4 cols (2 pairs)
#pragma unroll
    for (int i = 0; i < 8; i++) { acc[i][0] = 0ull; acc[i][1] = 0ull; }
    __syncthreads();

    for (int kt = 0; kt < SQ; kt += 64) {
        // Load K (d-major) and V (row-major): 64 rows x 64 d
        {
            const int lr = tid >> 2;
            const int ld0 = (tid & 3) * 16;
            const float* krow = Kb + (size_t)(kt + lr) * D + ld0;
            const float* vrow = Vb + (size_t)(kt + lr) * D + ld0;
#pragma unroll
            for (int i4 = 0; i4 < 4; i4++) {
                float4 kv = *(const float4*)(krow + i4 * 4);
                int d = ld0 + i4 * 4;
                Ks[(d + 0) * KP + lr] = kv.x;
                Ks[(d + 1) * KP + lr] = kv.y;
                Ks[(d + 2) * KP + lr] = kv.z;
                Ks[(d + 3) * KP + lr] = kv.w;
                float4 vv = *(const float4*)(vrow + i4 * 4);
                *(float4*)&Vs[lr * KP + ld0 + i4 * 4] = vv;
            }
        }
        __syncthreads();

        // Phase A: S = (Q*scale) @ K^T   rows packed in pairs
        {
            u64 s[4][4];
#pragma unroll
            for (int i = 0; i < 4; i++)
#pragma unroll
                for (int j = 0; j < 4; j++) s[i][j] = 0ull;
#pragma unroll
            for (int d = 0; d < 64; d++) {
                double2 A0 = *(const double2*)&Qs[d * QP + ty * 8];
                double2 A1 = *(const double2*)&Qs[d * QP + ty * 8 + 4];
                float4 kv = *(const float4*)&Ks[d * KP + tx * 4];
                u64 a[4] = {dtou(A0.x), dtou(A0.y), dtou(A1.x), dtou(A1.y)};
                u64 bj[4] = {splat2(kv.x), splat2(kv.y), splat2(kv.z), splat2(kv.w)};
#pragma unroll
                for (int i = 0; i < 4; i++)
#pragma unroll
                    for (int j = 0; j < 4; j++)
                        ffma2(s[i][j], a[i], bj[j]);
            }
#pragma unroll
            for (int i2 = 0; i2 < 4; i2++) {
                float2 v0 = unpack2(s[i2][0]);
                float2 v1 = unpack2(s[i2][1]);
                float2 v2 = unpack2(s[i2][2]);
                float2 v3 = unpack2(s[i2][3]);
                *(float4*)&Ss[(ty * 8 + 2 * i2) * SP + tx * 4] =
                    make_float4(v0.x, v1.x, v2.x, v3.x);
                *(float4*)&Ss[(ty * 8 + 2 * i2 + 1) * SP + tx * 4] =
                    make_float4(v0.y, v1.y, v2.y, v3.y);
            }
        }
        __syncthreads();

        // Online softmax: row r = tid>>1, half = tid&1 handles 32 cols.
        // Writes duplicated probabilities into Pd.
        {
            const int r = tid >> 1, half = tid & 1;
            const float* base = &Ss[r * SP + half * 32];
            float p[32];
            float mloc = -INFINITY;
#pragma unroll
            for (int i4 = 0; i4 < 8; i4++) {
                float4 sv = *(const float4*)(base + i4 * 4);
                p[i4 * 4 + 0] = sv.x; p[i4 * 4 + 1] = sv.y;
                p[i4 * 4 + 2] = sv.z; p[i4 * 4 + 3] = sv.w;
                mloc = fmaxf(mloc, fmaxf(fmaxf(sv.x, sv.y), fmaxf(sv.z, sv.w)));
            }
            mloc = fmaxf(mloc, __shfl_xor_sync(0xffffffffu, mloc, 1));
            float m_new = fmaxf(m_team, mloc);
            float alpha = __expf(m_team - m_new);
            float lsum = 0.0f;
#pragma unroll
            for (int i = 0; i < 32; i++) {
                p[i] = __expf(p[i] - m_new);
                lsum += p[i];
            }
            lsum += __shfl_xor_sync(0xffffffffu, lsum, 1);
            l_team = l_team * alpha + lsum;
            m_team = m_new;
            float* pd = &Pd[r * PDP + 2 * (half * 32)];
#pragma unroll
            for (int i4 = 0; i4 < 8; i4++) {
                double2 d0, d1;
                d0.x = __longlong_as_double((long long)splat2(p[i4 * 4 + 0]));
                d0.y = __longlong_as_double((long long)splat2(p[i4 * 4 + 1]));
                d1.x = __longlong_as_double((long long)splat2(p[i4 * 4 + 2]));
                d1.y = __longlong_as_double((long long)splat2(p[i4 * 4 + 3]));
                *(double2*)(pd + i4 * 8)     = d0;
                *(double2*)(pd + i4 * 8 + 4) = d1;
            }
            if (half == 0) alpha_s[r] = alpha;
        }
        __syncthreads();

        // Phase C: O = O*alpha + P @ V   (cols packed in pairs)
        {
#pragma unroll
            for (int i = 0; i < 8; i++) {
                u64 al = splat2(alpha_s[ty * 8 + i]);
                acc[i][0] = fmul2(acc[i][0], al);
                acc[i][1] = fmul2(acc[i][1], al);
            }
#pragma unroll
            for (int k = 0; k < 64; k++) {
                double2 vv = *(const double2*)&Vs[k * KP + tx * 4];
                u64 v0 = dtou(vv.x), v1 = dtou(vv.y);
#pragma unroll
                for (int i = 0; i < 8; i++) {
                    u64 pp = (u64)__double_as_longlong(
                        *(const double*)&Pd[(ty * 8 + i) * PDP + 2 * k]);
                    ffma2(acc[i][0], pp, v0);
                    ffma2(acc[i][1], pp, v1);
                }
            }
        }
        __syncthreads();   // protect tiles for next iteration
    }

    // Final normalize + store
    if ((tid & 1) == 0) l_s[tid >> 1] = l_team;
    __syncthreads();
    float* Ob = g_ctx + (size_t)(b * SQ + q0) * D + h * HDIM;
#pragma unroll
    for (int i = 0; i < 8; i++) {
        float inv = 1.0f / l_s[ty * 8 + i];
        float2 o0 = unpack2(acc[i][0]);
        float2 o1 = unpack2(acc[i][1]);
        *(float4*)&Ob[(size_t)(ty * 8 + i) * D + tx * 4] =
            make_float4(o0.x * inv, o0.y * inv, o1.x * inv, o1.y * inv);
    }
}

// ---------------------------------------------------------------------------
extern "C" void kernel_launch(void* const* d_in, const int* in_sizes, int n_in,
                              void* d_out, int out_size) {
    const float* x    = (const float*)d_in[0];
    const float* QW_w = (const float*)d_in[1];
    const float* QW_b = (const float*)d_in[2];
    const float* KW_w = (const float*)d_in[3];
    const float* KW_b = (const float*)d_in[4];
    const float* VW_w = (const float*)d_in[5];
    const float* VW_b = (const float*)d_in[6];
    const float* OW_w = (const float*)d_in[7];
    const float* OW_b = (const float*)d_in[8];
    float* out = (float*)d_out;

    cudaFuncSetAttribute(attn_kernel,
                         cudaFuncAttributeMaxDynamicSharedMemorySize,
                         ATTN_SMEM_BYTES);

    dim3 gq(D / BN, MTOT / BM, 3);     // (6, 64, 3)
    qkv_gemm<<<gq, 256>>>(x, QW_w, QW_b, KW_w, KW_b, VW_w, VW_b);

    dim3 ga(SQ / 128, BATCH * NH);     // (16, 48)
    attn_kernel<<<ga, 256, ATTN_SMEM_BYTES>>>();

    dim3 go(D / BN, MTOT / BM);        // (6, 64)
    out_gemm<<<go, 256>>>(OW_w, OW_b, out);
}